// round 12
// baseline (speedup 1.0000x reference)
#include <cuda_runtime.h>
#include <math.h>

#define B_ROWS 65536
#define C_COLS 1000
#define ROWS_PER_CTA 4
#define TILE_BYTES (ROWS_PER_CTA * C_COLS * 4)   // 16000 B per tensor
#define LOG2E_F 1.4426950408889634f

__device__ float g_rowloss[B_ROWS];
__device__ float g_partial[64];

typedef unsigned long long ull;

__device__ __forceinline__ ull pk2(float lo, float hi) {
    ull r; asm("mov.b64 %0, {%1, %2};" : "=l"(r) : "f"(lo), "f"(hi)); return r;
}
__device__ __forceinline__ void upk2(ull v, float& lo, float& hi) {
    asm("mov.b64 {%0, %1}, %2;" : "=f"(lo), "=f"(hi) : "l"(v));
}
__device__ __forceinline__ ull mul2(ull a, ull b) {
    ull d; asm("mul.rn.f32x2 %0, %1, %2;" : "=l"(d) : "l"(a), "l"(b)); return d;
}
__device__ __forceinline__ ull add2(ull a, ull b) {
    ull d; asm("add.rn.f32x2 %0, %1, %2;" : "=l"(d) : "l"(a), "l"(b)); return d;
}
__device__ __forceinline__ ull fma2(ull a, ull b, ull c) {
    ull d; asm("fma.rn.f32x2 %0, %1, %2, %3;" : "=l"(d) : "l"(a), "l"(b), "l"(c)); return d;
}
__device__ __forceinline__ float ex2f(float x) {
    float r; asm("ex2.approx.ftz.f32 %0, %1;" : "=f"(r) : "f"(x)); return r;
}
__device__ __forceinline__ unsigned smem_u32(const void* p) {
    unsigned a;
    asm("{ .reg .u64 t; cvta.to.shared.u64 t, %1; cvt.u32.u64 %0, t; }" : "=r"(a) : "l"(p));
    return a;
}
__device__ __forceinline__ float warpSum(float v) {
    #pragma unroll
    for (int k = 16; k; k >>= 1) v += __shfl_xor_sync(0xffffffffu, v, k);
    return v;
}

// TMA-staged single-pass moment kernel.
// CTA covers 4 CONTIGUOUS rows (16000 B per tensor) -> two 1-D cp.async.bulk
// copies into smem, mbarrier-signaled. Compute (packed f32x2, R11 core) reads
// from smem; no register front-batch -> ~46 regs -> 5 CTAs/SM.
__global__ __launch_bounds__(256)
void mvce_tma_kernel(const float* __restrict__ outp, const float* __restrict__ tgtp)
{
    __shared__ alignas(16) float s_o[ROWS_PER_CTA * C_COLS];
    __shared__ alignas(16) float s_t[ROWS_PER_CTA * C_COLS];
    __shared__ alignas(8)  ull  s_mbar;
    __shared__ float red[8][8];

    const int tid  = threadIdx.x;
    const int lane = tid & 31;
    const int w    = tid >> 5;
    const int pair = w >> 1;          // row within CTA (0..3)
    const int half = w & 1;           // half of the row
    const int row  = blockIdx.x * ROWS_PER_CTA + pair;

    const unsigned mbar = smem_u32(&s_mbar);

    if (tid == 0) {
        asm volatile("mbarrier.init.shared.b64 [%0], 1;" :: "r"(mbar) : "memory");
    }
    __syncthreads();

    if (tid == 0) {
        asm volatile("mbarrier.arrive.expect_tx.shared.b64 _, [%0], %1;"
                     :: "r"(mbar), "r"(2 * TILE_BYTES) : "memory");
        const float* src_o = outp + (size_t)blockIdx.x * (ROWS_PER_CTA * C_COLS);
        const float* src_t = tgtp + (size_t)blockIdx.x * (ROWS_PER_CTA * C_COLS);
        asm volatile("cp.async.bulk.shared::cta.global.mbarrier::complete_tx::bytes [%0], [%1], %2, [%3];"
                     :: "r"(smem_u32(s_o)), "l"(src_o), "r"(TILE_BYTES), "r"(mbar) : "memory");
        asm volatile("cp.async.bulk.shared::cta.global.mbarrier::complete_tx::bytes [%0], [%1], %2, [%3];"
                     :: "r"(smem_u32(s_t)), "l"(src_t), "r"(TILE_BYTES), "r"(mbar) : "memory");
    }

    // Wait for TMA completion (parity 0), acquire semantics for the LDS reads.
    {
        unsigned done;
        asm volatile(
            "{\n\t.reg .pred p;\n\t"
            "mbarrier.try_wait.parity.acquire.cta.shared::cta.b64 p, [%1], 0;\n\t"
            "selp.b32 %0, 1, 0, p;\n\t}"
            : "=r"(done) : "r"(mbar) : "memory");
        if (!done) {
            asm volatile(
                "{\n\t.reg .pred P1;\n\t"
                "WL_%=:\n\t"
                "mbarrier.try_wait.parity.acquire.cta.shared::cta.b64 P1, [%0], 0, 0x989680;\n\t"
                "@P1 bra.uni WD_%=;\n\t"
                "bra.uni WL_%=;\n\t"
                "WD_%=:\n\t}" :: "r"(mbar) : "memory");
        }
    }

    // Per-warp view: float4 index base within CTA tile.
    const float4* o4 = reinterpret_cast<const float4*>(s_o) + pair * 250 + half * 125;
    const float4* t4 = reinterpret_cast<const float4*>(s_t) + pair * 250 + half * 125;

    const ull LOG2E2 = pk2(LOG2E_F, LOG2E_F);
    ull Sall2 = 0, Tall2 = 0, TO2 = 0, E12 = 0, F12 = 0, TOp2 = 0, Tpos2 = 0, np2 = 0;

    #pragma unroll
    for (int k = 0; k < 4; k++) {
        float4 o, t;
        if (k < 3 || lane < 29) {
            o = o4[lane + k * 32];
            t = t4[lane + k * 32];
        } else {
            o = make_float4(-1e30f, -1e30f, -1e30f, -1e30f);   // ex2 -> 0
            t = make_float4(0.f, 0.f, 0.f, 0.f);               // mask 0, negative
        }
        #pragma unroll
        for (int h = 0; h < 2; h++) {
            const float oa = h ? o.z : o.x;
            const float ob = h ? o.w : o.y;
            const float ta = h ? t.z : t.x;
            const float tb = h ? t.w : t.y;

            const ull oo = pk2(oa, ob);
            const ull tt = pk2(ta, tb);

            float xa, xb;
            upk2(mul2(oo, LOG2E2), xa, xb);
            const ull ee = pk2(ex2f(xa), ex2f(xb));
            const ull mm = pk2(rintf(ta), rintf(tb));

            const ull to = mul2(tt, oo);
            const ull te = mul2(tt, ee);

            Sall2 = add2(Sall2, ee);
            Tall2 = add2(Tall2, tt);
            TO2   = add2(TO2, to);
            E12   = fma2(mm, ee, E12);
            F12   = fma2(mm, te, F12);
            TOp2  = fma2(mm, to, TOp2);
            Tpos2 = fma2(mm, tt, Tpos2);
            np2   = add2(np2, mm);
        }
    }

    float a0, a1;
    upk2(Sall2, a0, a1); float Sall = a0 + a1;
    upk2(Tall2, a0, a1); float Tall = a0 + a1;
    upk2(TO2,   a0, a1); float TO   = a0 + a1;
    upk2(E12,   a0, a1); float E1   = a0 + a1;
    upk2(F12,   a0, a1); float F1   = a0 + a1;
    upk2(TOp2,  a0, a1); float TOp  = a0 + a1;
    upk2(Tpos2, a0, a1); float Tpos = a0 + a1;
    upk2(np2,   a0, a1); float np   = a0 + a1;

    Sall = warpSum(Sall); Tall = warpSum(Tall); TO = warpSum(TO);
    E1 = warpSum(E1); F1 = warpSum(F1); TOp = warpSum(TOp);
    Tpos = warpSum(Tpos); np = warpSum(np);

    if (lane == 0) {
        red[w][0] = Sall; red[w][1] = Tall; red[w][2] = TO;  red[w][3] = E1;
        red[w][4] = F1;   red[w][5] = TOp;  red[w][6] = Tpos; red[w][7] = np;
    }
    __syncthreads();

    if (half == 0 && lane == 0) {
        const int p = w ^ 1;
        Sall += red[p][0]; Tall += red[p][1]; TO   += red[p][2]; E1 += red[p][3];
        F1   += red[p][4]; TOp  += red[p][5]; Tpos += red[p][6]; np += red[p][7];

        const float S = Sall - E1;
        const float T = Tall - Tpos;
        const float A = TO - TOp;
        const float r = __fdividef(1.0f, S);
        const float L = __logf(S);

        float rl;
        if (np > 0.f) {
            const float PL = L * fmaf(np, T, Tpos) + r * fmaf(T, E1, F1);
            rl = (PL - (np - 1.0f) * A - TO) / np;
        } else {
            rl = T * L - A;
        }
        g_rowloss[row] = rl;
    }
}

// ---- Final reduction, stage A: 64 blocks x 256 threads, float4 reads ----
__global__ __launch_bounds__(256)
void mvce_reduceA_kernel()
{
    __shared__ float s[8];
    const int tid  = threadIdx.x;
    const int lane = tid & 31;
    const int wid  = tid >> 5;

    const float4* rl4 = reinterpret_cast<const float4*>(g_rowloss);
    float4 v = rl4[blockIdx.x * 256 + tid];
    float acc = (v.x + v.y) + (v.z + v.w);
    acc = warpSum(acc);
    if (lane == 0) s[wid] = acc;
    __syncthreads();
    if (tid < 8) {
        float x = s[tid];
        #pragma unroll
        for (int k = 4; k; k >>= 1) x += __shfl_xor_sync(0xffu, x, k);
        if (tid == 0) g_partial[blockIdx.x] = x;
    }
}

// ---- Final reduction, stage B: single block of 64 threads ----
__global__ __launch_bounds__(64)
void mvce_reduceB_kernel(float* __restrict__ result)
{
    __shared__ float s[2];
    const int tid = threadIdx.x;
    float acc = g_partial[tid];
    acc = warpSum(acc);
    if ((tid & 31) == 0) s[tid >> 5] = acc;
    __syncthreads();
    if (tid == 0) result[0] = (s[0] + s[1]) / (float)B_ROWS;
}

extern "C" void kernel_launch(void* const* d_in, const int* in_sizes, int n_in,
                              void* d_out, int out_size)
{
    const float* output = (const float*)d_in[0];
    const float* target = (const float*)d_in[1];
    float* result = (float*)d_out;

    mvce_tma_kernel<<<B_ROWS / ROWS_PER_CTA, 256>>>(output, target);
    mvce_reduceA_kernel<<<64, 256>>>();
    mvce_reduceB_kernel<<<1, 64>>>(result);
}